// round 17
// baseline (speedup 1.0000x reference)
#include <cuda_runtime.h>
#include <cstdint>

#define NQ   4
#define DIM  16
#define NC   4
#define BLK  256
#define GRID 148                                 // 1 block/SM, all co-resident
#define CHUNK_SAMPLES 64
#define CHUNK_BYTES (CHUNK_SAMPLES * 576)        // 36864
#define NBUF 5
#define PART_PITCH 9
#define MAX_G 7                                  // max units per block (ceil 1024/148)

// smem layout (bytes)
#define OFF_BUF   0
#define OFF_PART  (NBUF * CHUNK_BYTES)                  // 184320 (256*9*4 = 9216)
#define OFF_LSM   (OFF_PART + 256 * PART_PITCH * 4)     // 193536 (7*256*16 = 28672)
#define OFF_MBAR  (OFF_LSM + MAX_G * 256 * 16)          // 222208 (5*8 = 40)
#define SMEM_BYTES (OFF_MBAR + NBUF * 8)                // 222248

__device__ double g_part[GRID * 8];              // write-slots: no init kernel needed
__device__ float  g_scale[NC];
__device__ float  g_shift[NC];
__device__ unsigned g_cnt;                       // monotonic across launches
__device__ volatile int g_flag;                  // generation flag, monotonic

__device__ __forceinline__ void mbar_init(uint32_t mbar, uint32_t count) {
    asm volatile("mbarrier.init.shared.b64 [%0], %1;" :: "r"(mbar), "r"(count) : "memory");
}
__device__ __forceinline__ void bulk_issue(uint32_t dst, const char* src, uint32_t mbar) {
    asm volatile("mbarrier.arrive.expect_tx.shared.b64 _, [%0], %1;"
                 :: "r"(mbar), "r"((uint32_t)CHUNK_BYTES) : "memory");
    asm volatile("cp.async.bulk.shared::cluster.global.mbarrier::complete_tx::bytes "
                 "[%0], [%1], %2, [%3];"
                 :: "r"(dst), "l"(src), "r"((uint32_t)CHUNK_BYTES), "r"(mbar) : "memory");
}
__device__ __forceinline__ void mbar_wait(uint32_t mbar, uint32_t parity) {
    uint32_t done;
    do {
        asm volatile("{\n\t.reg .pred p;\n\t"
            "mbarrier.try_wait.parity.acquire.cta.shared::cta.b64 p, [%1], %2, 0x989680;\n\t"
            "selp.b32 %0, 1, 0, p;\n\t}"
            : "=r"(done) : "r"(mbar), "r"(parity) : "memory");
    } while (!done);
}

__global__ void __launch_bounds__(BLK, 1) k_persist(
    const float* __restrict__ x,
    const float* __restrict__ wts,
    const float* __restrict__ W,
    const float* __restrict__ bias,
    const float* __restrict__ gamma,
    const float* __restrict__ beta,
    float* __restrict__ out,
    int units, float invB)               // units = B/256 = 1024
{
    extern __shared__ char smem[];
    float* part = (float*)(smem + OFF_PART);
    float* lsm  = (float*)(smem + OFF_LSM);
    const uint32_t smem_u32 = (uint32_t)__cvta_generic_to_shared(smem);
    const uint32_t mbar0 = smem_u32 + OFF_MBAR;

    const int t = threadIdx.x;
    const int b = blockIdx.x;

    // units for this block: u = b + it*GRID, it < myU
    int myU = 0;
    #pragma unroll
    for (int it = 0; it < MAX_G; it++) if (b + it * GRID < units) myU = it + 1;
    const int myChunks = myU * 4;

    // constants in registers
    float wc[8], ws[8];
    #pragma unroll
    for (int i = 0; i < 8; i++) __sincosf(__ldg(&wts[i]) * 0.5f, &ws[i], &wc[i]);
    float Wr[16], bi[4];
    #pragma unroll
    for (int i = 0; i < 16; i++) Wr[i] = __ldg(&W[i]);
    #pragma unroll
    for (int i = 0; i < 4; i++)  bi[i] = __ldg(&bias[i]);

    // chunk c -> global source
    auto chunk_src = [&](int c) -> const char* {
        size_t unit = (size_t)(b + (c >> 2) * GRID);
        return (const char*)x + (unit * 256 + (size_t)(c & 3) * CHUNK_SAMPLES) * 576;
    };

    // init mbarriers
    if (t == 0) {
        #pragma unroll
        for (int i = 0; i < NBUF; i++) mbar_init(mbar0 + 8 * i, 1);
    }
    __syncthreads();

    // prologue: queue 4 chunks on the TMA engine
    if (t == 0) {
        #pragma unroll
        for (int c = 0; c < 4; c++)
            if (c < myChunks)
                bulk_issue(smem_u32 + (c % NBUF) * CHUNK_BYTES, chunk_src(c), mbar0 + 8 * (c % NBUF));
    }

    // pooling identity for this thread
    const int ps = t & 63;               // sample within chunk
    const int pq = t >> 6;               // quarter (3 image rows)
    const int crot = (t >> 1) & 3;       // column rotation group (conflict avoidance)

    float sum0=0.f,sum1=0.f,sum2=0.f,sum3=0.f, sq0=0.f,sq1=0.f,sq2=0.f,sq3=0.f;

    #pragma unroll 1
    for (int c = 0; c < myChunks; c++) {
        const int bi5 = c % NBUF;
        mbar_wait(mbar0 + 8 * bi5, (uint32_t)((c / NBUF) & 1));

        // ---- pool this chunk from smem (rotated columns, ~conflict-free) ----
        {
            const float* rowp = (const float*)(smem + bi5 * CHUNK_BYTES + ps * 576 + pq * 144);
            float L = 0.f, R = 0.f;
            #pragma unroll
            for (int k = 0; k < 9; k++) {
                int j = crot + k; if (j >= 9) j -= 9;
                float4 v = *(const float4*)(rowp + 4 * j);
                int pos = j - 3 * ((j >= 3) + (j >= 6));
                float sa = v.x + v.y, sb = v.z + v.w;
                if (pos == 0)      { L += sa + sb; }
                else if (pos == 1) { L += sa; R += sb; }
                else               { R += sa + sb; }
            }
            float* pd = part + (unsigned)((c & 3) * 64 + ps) * PART_PITCH + 2u * pq;
            pd[0] = L; pd[1] = R;
        }
        __syncthreads();

        // refill this ring slot 4 ahead (TMA engine keeps streaming during circuit)
        if (t == 0 && c + 4 < myChunks)
            bulk_issue(smem_u32 + ((c + 4) % NBUF) * CHUNK_BYTES, chunk_src(c + 4),
                       mbar0 + 8 * ((c + 4) % NBUF));

        if ((c & 3) == 3) {
            const int it = c >> 2;
            // ---- per-thread sample circuit (fused RX+RY1; final CZ dropped) ----
            const float* pp = part + (unsigned)t * PART_PITCH;
            float TL = pp[0] + pp[2], TR = pp[1] + pp[3];
            float BL = pp[4] + pp[6], BR = pp[5] + pp[7];

            const float inv72 = 1.f / 72.f;
            float cp4[4], sp4[4];
            __sincosf(TL * inv72, &sp4[0], &cp4[0]);
            __sincosf(TR * inv72, &sp4[1], &cp4[1]);
            __sincosf(BL * inv72, &sp4[2], &cp4[2]);
            __sincosf(BR * inv72, &sp4[3], &cp4[3]);

            float v0r[4], v0i[4], v1r[4], v1i[4];
            #pragma unroll
            for (int i = 0; i < 4; i++) {
                float cw = wc[i], sw = ws[i];
                v0r[i] =  cw * cp4[i];  v0i[i] =  sw * sp4[i];
                v1r[i] =  sw * cp4[i];  v1i[i] = -cw * sp4[i];
            }
            float p01r[4], p01i[4], p23r[4], p23i[4];
            #pragma unroll
            for (int a = 0; a < 2; a++) {
                float ar0 = a ? v1r[0] : v0r[0], ai0 = a ? v1i[0] : v0i[0];
                float ar2 = a ? v1r[2] : v0r[2], ai2 = a ? v1i[2] : v0i[2];
                #pragma unroll
                for (int cc = 0; cc < 2; cc++) {
                    float br1 = cc ? v1r[1] : v0r[1], bi1 = cc ? v1i[1] : v0i[1];
                    float br3 = cc ? v1r[3] : v0r[3], bi3 = cc ? v1i[3] : v0i[3];
                    p01r[a*2+cc] = ar0 * br1 - ai0 * bi1;
                    p01i[a*2+cc] = ar0 * bi1 + ai0 * br1;
                    p23r[a*2+cc] = ar2 * br3 - ai2 * bi3;
                    p23i[a*2+cc] = ar2 * bi3 + ai2 * br3;
                }
            }
            float re[DIM], im[DIM];
            #pragma unroll
            for (int k = 0; k < DIM; k++) {
                int a = (k >> 2) & 3, cc = k & 3;
                float rr = p01r[a] * p23r[cc] - p01i[a] * p23i[cc];
                float ii = p01r[a] * p23i[cc] + p01i[a] * p23r[cc];
                int par = (((k >> 3) & (k >> 2)) ^ ((k >> 2) & (k >> 1)) ^ ((k >> 1) & k)) & 1;
                re[k] = par ? -rr : rr;
                im[k] = par ? -ii : ii;
            }
            #pragma unroll
            for (int w = 0; w < NQ; w++) {
                float cc2 = wc[4 + w], ss2 = ws[4 + w];
                int bit = 1 << (3 - w);
                #pragma unroll
                for (int k = 0; k < DIM; k++) {
                    if (!(k & bit)) {
                        int k1 = k | bit;
                        float r0 = re[k], r1 = re[k1];
                        re[k]  = cc2 * r0 - ss2 * r1;
                        re[k1] = ss2 * r0 + cc2 * r1;
                        float i0 = im[k], i1 = im[k1];
                        im[k]  = cc2 * i0 - ss2 * i1;
                        im[k1] = ss2 * i0 + cc2 * i1;
                    }
                }
            }
            float q0=0.f, q1=0.f, q2=0.f, q3=0.f;
            #pragma unroll
            for (int k = 0; k < DIM; k++) {
                float p = re[k] * re[k] + im[k] * im[k];
                q0 += (k & 8) ? -p : p;
                q1 += (k & 4) ? -p : p;
                q2 += (k & 2) ? -p : p;
                q3 += (k & 1) ? -p : p;
            }
            float l0 = bi[0] + q0*Wr[0]  + q1*Wr[1]  + q2*Wr[2]  + q3*Wr[3];
            float l1 = bi[1] + q0*Wr[4]  + q1*Wr[5]  + q2*Wr[6]  + q3*Wr[7];
            float l2 = bi[2] + q0*Wr[8]  + q1*Wr[9]  + q2*Wr[10] + q3*Wr[11];
            float l3 = bi[3] + q0*Wr[12] + q1*Wr[13] + q2*Wr[14] + q3*Wr[15];

            *(float4*)(lsm + (unsigned)(it * 256 + t) * 4u) = make_float4(l0, l1, l2, l3);
            sum0 += l0; sum1 += l1; sum2 += l2; sum3 += l3;
            sq0 += l0*l0; sq1 += l1*l1; sq2 += l2*l2; sq3 += l3*l3;

            __syncthreads();     // circuit reads of part done before next unit's pools
        }
    }

    // ---- block reduction (reuse part area) ----
    float* rsm  = part;                       // 64 floats
    double* dsm = (double*)(part + 64);       // 8 doubles (8B aligned)
    int* ctrl   = (int*)(part + 80);

    float red[8] = {sum0,sum1,sum2,sum3,sq0,sq1,sq2,sq3};
    #pragma unroll
    for (int off = 16; off > 0; off >>= 1) {
        #pragma unroll
        for (int j = 0; j < 8; j++)
            red[j] += __shfl_down_sync(0xFFFFFFFFu, red[j], off);
    }
    __syncthreads();
    int lane = t & 31, wid = t >> 5;
    if (lane == 0) {
        #pragma unroll
        for (int j = 0; j < 8; j++) rsm[j * 8 + wid] = red[j];
    }
    __syncthreads();
    if (t < 8) {
        float acc = 0.f;
        #pragma unroll
        for (int wgi = 0; wgi < 8; wgi++) acc += rsm[t * 8 + wgi];
        g_part[b * 8 + t] = (double)acc;
        __threadfence();
    }
    __syncthreads();

    // ---- generation grid barrier (148 blocks, 1/SM; monotonic, no init kernel) ----
    if (t == 0) {
        unsigned r = atomicAdd(&g_cnt, 1u);
        ctrl[0] = (r % GRID == GRID - 1u) ? 1 : 0;
        ctrl[1] = (int)(r / GRID);
        __threadfence();
    }
    __syncthreads();
    int isLast = ctrl[0], gen = ctrl[1];

    if (isLast) {
        if (t < 64) {
            int c = t >> 3, j = t & 7;
            double acc = 0.0;
            for (int bb = j; bb < GRID; bb += 8) acc += g_part[bb * 8 + c];
            acc += __shfl_xor_sync(0xFFFFFFFFu, acc, 1);
            acc += __shfl_xor_sync(0xFFFFFFFFu, acc, 2);
            acc += __shfl_xor_sync(0xFFFFFFFFu, acc, 4);
            if (j == 0) dsm[c] = acc;
        }
        __syncthreads();
        if (t < 4) {
            double m = dsm[t] * (double)invB;
            double v = dsm[4 + t] * (double)invB - m * m;
            float inv = rsqrtf((float)v + 1e-5f);
            g_scale[t] = __ldg(&gamma[t]) * inv;
            g_shift[t] = __ldg(&beta[t]) - (float)m * inv * __ldg(&gamma[t]);
        }
        __threadfence();
        __syncthreads();
        if (t == 0) atomicExch((int*)&g_flag, gen + 1);
    } else {
        if (t == 0) {
            while (g_flag < gen + 1) __nanosleep(64);
        }
    }
    __syncthreads();

    float sc[4], sh[4];
    #pragma unroll
    for (int c2 = 0; c2 < NC; c2++) {
        sc[c2] = *((volatile float*)&g_scale[c2]);
        sh[c2] = *((volatile float*)&g_shift[c2]);
    }

    // ---- coalesced normalized write from smem-held logits ----
    float4* o4 = (float4*)out;
    #pragma unroll 1
    for (int it = 0; it < MAX_G; it++) {
        if (it < myU) {
            int u = b + it * GRID;
            float4 l = *(const float4*)(lsm + (unsigned)(it * 256 + t) * 4u);
            o4[(size_t)u * 256 + t] =
                make_float4(l.x*sc[0]+sh[0], l.y*sc[1]+sh[1], l.z*sc[2]+sh[2], l.w*sc[3]+sh[3]);
        }
    }
}

extern "C" void kernel_launch(void* const* d_in, const int* in_sizes, int n_in,
                              void* d_out, int out_size) {
    const float* x     = (const float*)d_in[0];
    const float* wts   = (const float*)d_in[1];
    const float* W     = (const float*)d_in[2];
    const float* bias  = (const float*)d_in[3];
    const float* gamma = (const float*)d_in[4];
    const float* beta  = (const float*)d_in[5];
    float* out = (float*)d_out;

    int B = in_sizes[0] / 144;          // 262144
    int units = B / 256;                // 1024

    cudaFuncSetAttribute(k_persist, cudaFuncAttributeMaxDynamicSharedMemorySize, SMEM_BYTES);

    k_persist<<<GRID, BLK, SMEM_BYTES>>>(x, wts, W, bias, gamma, beta, out,
                                         units, 1.0f / (float)B);
}